// round 6
// baseline (speedup 1.0000x reference)
#include <cuda_runtime.h>
#include <math.h>
#include <stdint.h>

#define B    4
#define N    16384
#define CIN  4
#define SD   3
#define W    256
#define L    8
#define M    32
#define H    8
#define FF   1024
#define TF   4
#define DH   32
#define TOK1 32
#define TOKF 64

__device__ float g_x[(size_t)B * N * W];
__device__ float g_w[(size_t)B * N * M];
__device__ float g_z[(size_t)L * B * M * W];     // per-layer (zeroed once per launch)
__device__ float g_wsum[L * B * M];
__device__ float g_zp[B * M * W];
__device__ float g_w1t[(size_t)L * FF * W];      // [L][FF][Wperm] tf32
__device__ float g_w2t[(size_t)L * W * FF];      // [L][W][FFperm] tf32

// ---------- helpers ----------
__device__ __forceinline__ float to_tf32(float x) {
    uint32_t r; asm("cvt.rna.tf32.f32 %0, %1;" : "=r"(r) : "f"(x));
    return __uint_as_float(r);
}
__device__ __forceinline__ int kperm(int k) {
    return (k & ~7) | ((k & 3) << 1) | ((k >> 2) & 1);
}
__device__ __forceinline__ int swz(int r, int k, int S) {
    return r * S + ((((k >> 3) ^ (r & 7)) << 3) | ((k & 3) << 1) | ((k >> 2) & 1));
}
__device__ __forceinline__ void mma8(float* d, const uint32_t* a, const uint32_t* b) {
    asm volatile("mma.sync.aligned.m16n8k8.row.col.f32.tf32.tf32.f32 "
        "{%0,%1,%2,%3}, {%4,%5,%6,%7}, {%8,%9}, {%0,%1,%2,%3};"
        : "+f"(d[0]), "+f"(d[1]), "+f"(d[2]), "+f"(d[3])
        : "r"(a[0]), "r"(a[1]), "r"(a[2]), "r"(a[3]), "r"(b[0]), "r"(b[1]));
}

// ---------------- K0: embed (16 tokens / block) ----------------
__global__ void __launch_bounds__(256) embed_kernel(
    const float* __restrict__ feat, const float* __restrict__ coords,
    const float* __restrict__ tn, const float* __restrict__ ew, const float* __restrict__ eb)
{
    __shared__ float f[16][16];
    int t0 = blockIdx.x * 16;
    int tid = threadIdx.x;
    {
        int t = tid >> 4, k = tid & 15;
        int token = t0 + t, b = token / N;
        float v = 0.f;
        if (k < CIN) v = feat[(size_t)token * CIN + k];
        else if (k < CIN + SD) v = coords[(size_t)token * SD + (k - CIN)];
        else if (k < 15) {
            int kk = k - 7, i = kk & 3;
            float ang = powf(1000.0f, -(float)i / (float)TF) * (tn[b] * 1000.0f);
            v = (kk < TF) ? sinf(ang) : cosf(ang);
        }
        f[t][k] = v;
    }
    __syncthreads();
    int c = tid;
    float wreg[15];
#pragma unroll
    for (int k = 0; k < 15; k++) wreg[k] = ew[k * W + c];
    float bias = eb[c];
#pragma unroll 4
    for (int t = 0; t < 16; t++) {
        float acc = bias;
#pragma unroll
        for (int k = 0; k < 15; k++) acc += f[t][k] * wreg[k];
        g_x[(size_t)(t0 + t) * W + c] = acc;
    }
}

// ---------------- weight transform + zero (fused) ----------------
__global__ void __launch_bounds__(256) w1t_kernel(const float* __restrict__ f1w)
{
    int idx = blockIdx.x * 256 + threadIdx.x;            // L*FF*W
    int l = idx / (FF * W), r = idx % (FF * W), j = r / W, c = r % W;
    g_w1t[((size_t)l * FF + j) * W + kperm(c)] =
        to_tf32(f1w[((size_t)l * W + c) * FF + j]);
}
#define NB_W2T (L * W * FF / 256)
#define NB_Z   (L * B * M * W / 256)
__global__ void __launch_bounds__(256) w2t_zero_kernel(const float* __restrict__ f2w)
{
    int bid = blockIdx.x;
    if (bid < NB_W2T) {
        int idx = bid * 256 + threadIdx.x;
        int l = idx / (W * FF), r = idx % (W * FF), c = r / FF, j = r % FF;
        g_w2t[((size_t)l * W + c) * FF + kperm(j)] =
            to_tf32(f2w[((size_t)l * FF + j) * W + c]);
    } else if (bid < NB_W2T + NB_Z) {
        int idx = (bid - NB_W2T) * 256 + threadIdx.x;
        g_z[idx] = 0.f;
    } else {
        for (int i = threadIdx.x; i < L * B * M; i += 256) g_wsum[i] = 0.f;
    }
}

// ---------------- K1: slice ----------------
__global__ void __launch_bounds__(256) slice_kernel(
    const float* __restrict__ ln_g, const float* __restrict__ ln_b,
    const float* __restrict__ sw, const float* __restrict__ sb, int layer)
{
    __shared__ float hs[TOK1][W];
    __shared__ float ws[TOK1][M];
    __shared__ float inv[TOK1];
    int nb = N / TOK1, b = blockIdx.x / nb, t0 = (blockIdx.x % nb) * TOK1;
    int tid = threadIdx.x, warp = tid >> 5, lane = tid & 31;
    const float* g = ln_g + layer * W;
    const float* be = ln_b + layer * W;
    float* zdst = g_z + (size_t)layer * B * M * W;
    float* wsdst = g_wsum + layer * B * M;

    for (int t = warp; t < TOK1; t += 8) {
        const float* xr = g_x + ((size_t)(b * N + t0 + t)) * W;
        float v[8]; float s = 0.f, s2 = 0.f;
#pragma unroll
        for (int i = 0; i < 8; i++) { v[i] = xr[lane + 32 * i]; s += v[i]; s2 += v[i] * v[i]; }
#pragma unroll
        for (int o = 16; o > 0; o >>= 1) {
            s += __shfl_xor_sync(0xffffffffu, s, o);
            s2 += __shfl_xor_sync(0xffffffffu, s2, o);
        }
        float mean = s * (1.0f / W), var = s2 * (1.0f / W) - mean * mean;
        float r = rsqrtf(var + 1e-5f);
#pragma unroll
        for (int i = 0; i < 8; i++) {
            int c = lane + 32 * i;
            hs[t][c] = (v[i] - mean) * r * g[c] + be[c];
        }
    }
    __syncthreads();
    const float* swl = sw + (size_t)layer * W * M;
    float lg[4];
#pragma unroll
    for (int r = 0; r < 4; r++) {
        int idx = tid + 256 * r, t = idx / M, m = idx % M;
        float acc = sb[layer * M + m];
#pragma unroll 8
        for (int c = 0; c < W; c++) acc += hs[t][c] * swl[c * M + m];
        lg[r] = acc;
    }
#pragma unroll
    for (int r = 0; r < 4; r++) { int idx = tid + 256 * r; ws[idx / M][idx % M] = lg[r]; }
    __syncthreads();
    if (tid < TOK1) {
        float mx = -1e30f;
#pragma unroll
        for (int m = 0; m < M; m++) mx = fmaxf(mx, ws[tid][m]);
        float sum = 0.f;
#pragma unroll
        for (int m = 0; m < M; m++) { float e = expf(ws[tid][m] - mx); ws[tid][m] = e; sum += e; }
        inv[tid] = 1.0f / sum;
    }
    __syncthreads();
#pragma unroll
    for (int r = 0; r < 4; r++) {
        int idx = tid + 256 * r, t = idx / M, m = idx % M;
        float v = ws[t][m] * inv[t];
        ws[t][m] = v;
        g_w[((size_t)(b * N + t0 + t)) * M + m] = v;
    }
    __syncthreads();
    if (tid < M) {
        float s = 0.f;
#pragma unroll
        for (int t = 0; t < TOK1; t++) s += ws[t][tid];
        atomicAdd(&wsdst[b * M + tid], s);
    }
    float zacc[M];
#pragma unroll
    for (int m = 0; m < M; m++) zacc[m] = 0.f;
    for (int t = 0; t < TOK1; t++) {
        float hv = hs[t][tid];
#pragma unroll
        for (int m = 0; m < M; m++) zacc[m] += ws[t][m] * hv;
    }
#pragma unroll
    for (int m = 0; m < M; m++) atomicAdd(&zdst[(b * M + m) * W + tid], zacc[m]);
}

// ---------------- K2: fused latent (qkv + attn + zp), one block per b ------
#define LAT_SMEM ((M * W + M * 3 * W + M * W) * 4)
__global__ void __launch_bounds__(512, 1) latent_kernel(
    const float* __restrict__ qkvw, const float* __restrict__ qkvb,
    const float* __restrict__ ow, const float* __restrict__ ob, int layer)
{
    extern __shared__ float ls[];
    float* zs = ls;                 // [32][256]
    float* qk = ls + M * W;         // [32][768]
    float* os = qk + M * 3 * W;     // [32][256]
    int b = blockIdx.x;
    int tid = threadIdx.x, warp = tid >> 5, lane = tid & 31;

    const float* zsrc = g_z + (size_t)layer * B * M * W + (size_t)b * M * W;
    const float* wsv = g_wsum + layer * B * M + b * M;
    for (int i = tid; i < M * W; i += 512) {
        int m = i >> 8;
        zs[i] = zsrc[i] / fmaxf(wsv[m], 1e-8f);
    }
    __syncthreads();

    const float* wq = qkvw + (size_t)layer * W * 3 * W;
    const float* bq = qkvb + layer * 3 * W;
    for (int i = tid; i < M * 3 * W; i += 512) {
        int m = i / (3 * W), j = i % (3 * W);
        float acc = bq[j];
        const float* zrow = zs + m * W;
#pragma unroll 8
        for (int c = 0; c < W; c++) acc += zrow[c] * wq[(size_t)c * (3 * W) + j];
        qk[i] = acc;
    }
    __syncthreads();

    if (warp < H) {
        int m = lane, h = warp;
        const float scale = 0.17677669529663687f;
        float qreg[DH], srow[M];
#pragma unroll
        for (int d = 0; d < DH; d++) qreg[d] = qk[m * (3 * W) + h * DH + d];
        float mx = -1e30f;
#pragma unroll
        for (int n = 0; n < M; n++) {
            float acc = 0.f;
#pragma unroll
            for (int d = 0; d < DH; d++) acc += qreg[d] * qk[n * (3 * W) + W + h * DH + d];
            acc *= scale;
            srow[n] = acc;
            mx = fmaxf(mx, acc);
        }
        float ssum = 0.f;
#pragma unroll
        for (int n = 0; n < M; n++) { srow[n] = expf(srow[n] - mx); ssum += srow[n]; }
        float is = 1.0f / ssum;
#pragma unroll
        for (int d = 0; d < DH; d++) {
            float acc = 0.f;
#pragma unroll
            for (int n = 0; n < M; n++) acc += srow[n] * qk[n * (3 * W) + 2 * W + h * DH + d];
            os[m * W + h * DH + d] = acc * is;
        }
    }
    __syncthreads();

    const float* wo = ow + (size_t)layer * W * W;
    const float* bo = ob + layer * W;
    for (int i = tid; i < M * W; i += 512) {
        int m = i >> 8, c = i & 255;
        float acc = bo[c];
        const float* orow = os + m * W;
#pragma unroll 8
        for (int k = 0; k < W; k++) acc += orow[k] * wo[(size_t)k * W + c];
        g_zp[(size_t)(b * M + m) * W + c] = acc;
    }
}

// ---------------- K3: FFN mma.sync tf32 (64 tok / 256 thr / 8 warps) -------
#define SMW_G  (TOKF * 256)                     // float offset of G
#define SM_FFN_BYTES ((TOKF * 256 + TOKF * 128) * 4)

__global__ void __launch_bounds__(256, 2) ffn_mma_kernel(
    const float* __restrict__ ln2g, const float* __restrict__ ln2b,
    const float* __restrict__ f1b, const float* __restrict__ f2b, int layer)
{
    extern __shared__ float sm[];
    float* s_h2 = sm;                 // [64][256] swizzled
    float* s_g  = sm + SMW_G;         // [64][128] swizzled
    int tid = threadIdx.x;
    int warp = tid >> 5, lane = tid & 31, g = lane >> 2, tig = lane & 3;
    int nb = N / TOKF, b = blockIdx.x / nb, t0 = (blockIdx.x % nb) * TOKF;
    size_t xbase = ((size_t)(b * N) + t0) * W;

    // ---- prologue: x_mid = x + w@zp ----
    int c = tid;
    float zpc[M];
#pragma unroll
    for (int m = 0; m < M; m++) zpc[m] = g_zp[(size_t)(b * M + m) * W + c];
    for (int i = tid; i < TOKF * M; i += 256)
        s_g[i] = g_w[((size_t)(b * N) + t0 + i / M) * M + (i % M)];
    __syncthreads();
    for (int t = 0; t < TOKF; t++) {
        float acc = g_x[xbase + (size_t)t * W + c];
#pragma unroll
        for (int m = 0; m < M; m++) acc += s_g[t * M + m] * zpc[m];
        g_x[xbase + (size_t)t * W + c] = acc;
        s_h2[swz(t, c, 256)] = acc;
    }
    __syncthreads();

    // ---- LN2 in place (tf32-rounded): 8 warps x 8 rows ----
    {
        const float* g2 = ln2g + layer * W;
        const float* b2 = ln2b + layer * W;
        for (int rr = 0; rr < 8; rr++) {
            int r = warp * 8 + rr;
            float v[8]; float s = 0.f, s2 = 0.f;
#pragma unroll
            for (int i = 0; i < 8; i++) {
                v[i] = s_h2[swz(r, lane + 32 * i, 256)];
                s += v[i]; s2 += v[i] * v[i];
            }
#pragma unroll
            for (int o = 16; o > 0; o >>= 1) {
                s += __shfl_xor_sync(0xffffffffu, s, o);
                s2 += __shfl_xor_sync(0xffffffffu, s2, o);
            }
            float mean = s * (1.0f / W), var = s2 * (1.0f / W) - mean * mean;
            float rs = rsqrtf(var + 1e-5f);
#pragma unroll
            for (int i = 0; i < 8; i++) {
                int cc = lane + 32 * i;
                s_h2[swz(r, cc, 256)] = to_tf32((v[i] - mean) * rs * g2[cc] + b2[cc]);
            }
        }
    }
    __syncthreads();

    const float* w1l = g_w1t + (size_t)layer * FF * W;
    const float* w2l = g_w2t + (size_t)layer * W * FF;
    const float* b1l = f1b + layer * FF;

    int wm = warp >> 2, wn = warp & 3;        // 2x4 warp grid
    float d2[2][8][4];
#pragma unroll
    for (int mt = 0; mt < 2; mt++)
#pragma unroll
        for (int nt = 0; nt < 8; nt++)
#pragma unroll
            for (int q = 0; q < 4; q++) d2[mt][nt][q] = 0.f;

    for (int chunk = 0; chunk < 8; chunk++) {
        int j0 = chunk * 128;

        // ===== GEMM1: D1[64x128] = h2 @ W1T(chunk), K=256 =====
        float d1[2][4][4];
#pragma unroll
        for (int mt = 0; mt < 2; mt++)
#pragma unroll
            for (int nt = 0; nt < 4; nt++)
#pragma unroll
                for (int q = 0; q < 4; q++) d1[mt][nt][q] = 0.f;

#pragma unroll 4
        for (int ks = 0; ks < 32; ks++) {
            int kx = ((ks ^ g) << 3) + 2 * tig;
            uint32_t af[2][4];
#pragma unroll
            for (int mt = 0; mt < 2; mt++) {
                int r0 = wm * 32 + mt * 16 + g;
                float2 v0 = *(const float2*)&s_h2[r0 * 256 + kx];
                float2 v1 = *(const float2*)&s_h2[(r0 + 8) * 256 + kx];
                af[mt][0] = __float_as_uint(v0.x);
                af[mt][1] = __float_as_uint(v1.x);
                af[mt][2] = __float_as_uint(v0.y);
                af[mt][3] = __float_as_uint(v1.y);
            }
#pragma unroll
            for (int nt = 0; nt < 4; nt++) {
                int j = j0 + wn * 32 + nt * 8 + g;
                float2 bv = *(const float2*)&w1l[(size_t)j * W + ks * 8 + 2 * tig];
                uint32_t bf[2] = { __float_as_uint(bv.x), __float_as_uint(bv.y) };
                mma8(d1[0][nt], af[0], bf);
                mma8(d1[1][nt], af[1], bf);
            }
        }
        __syncthreads();

        // ===== bias + gelu -> G (tf32) =====
#pragma unroll
        for (int mt = 0; mt < 2; mt++) {
#pragma unroll
            for (int nt = 0; nt < 4; nt++) {
                int row = wm * 32 + mt * 16 + g;
                int jc = wn * 32 + nt * 8 + 2 * tig;
#pragma unroll
                for (int q = 0; q < 4; q++) {
                    int rr = row + (q >> 1) * 8;
                    int jj = jc + (q & 1);
                    float x = d1[mt][nt][q] + b1l[j0 + jj];
                    float gl = 0.5f * x * (1.0f + erff(x * 0.7071067811865476f));
                    s_g[swz(rr, jj, 128)] = to_tf32(gl);
                }
            }
        }
        __syncthreads();

        // ===== GEMM2 partial: D2[64x256] += G @ W2T(chunk), K=128 =====
#pragma unroll 2
        for (int ks = 0; ks < 16; ks++) {
            int kx = ((ks ^ g) << 3) + 2 * tig;
            uint32_t af[2][4];
#pragma unroll
            for (int mt = 0; mt < 2; mt++) {
                int r0 = wm * 32 + mt * 16 + g;
                float2 v0 = *(const float2*)&s_g[r0 * 128 + kx];
                float2 v1 = *(const float2*)&s_g[(r0 + 8) * 128 + kx];
                af[mt][0] = __float_as_uint(v0.x);
                af[mt][1] = __float_as_uint(v1.x);
                af[mt][2] = __float_as_uint(v0.y);
                af[mt][3] = __float_as_uint(v1.y);
            }
#pragma unroll
            for (int nt = 0; nt < 8; nt++) {
                int cc = wn * 64 + nt * 8 + g;
                float2 bv = *(const float2*)&w2l[(size_t)cc * FF + j0 + ks * 8 + 2 * tig];
                uint32_t bf[2] = { __float_as_uint(bv.x), __float_as_uint(bv.y) };
                mma8(d2[0][nt], af[0], bf);
                mma8(d2[1][nt], af[1], bf);
            }
        }
    }

    // ---- epilogue: x = x_mid + D2 + b2 ----
    const float* b2l = f2b + layer * W;
#pragma unroll
    for (int mt = 0; mt < 2; mt++) {
#pragma unroll
        for (int nt = 0; nt < 8; nt++) {
            int col = wn * 64 + nt * 8 + 2 * tig;
            int ra = wm * 32 + mt * 16 + g;
            float2 xm = *(const float2*)&g_x[xbase + (size_t)ra * W + col];
            float2 o;
            o.x = xm.x + d2[mt][nt][0] + b2l[col];
            o.y = xm.y + d2[mt][nt][1] + b2l[col + 1];
            *(float2*)&g_x[xbase + (size_t)ra * W + col] = o;
            int rb = ra + 8;
            float2 xm2 = *(const float2*)&g_x[xbase + (size_t)rb * W + col];
            o.x = xm2.x + d2[mt][nt][2] + b2l[col];
            o.y = xm2.y + d2[mt][nt][3] + b2l[col + 1];
            *(float2*)&g_x[xbase + (size_t)rb * W + col] = o;
        }
    }
}

// ---------------- K5: final projection ----------------
__global__ void __launch_bounds__(256) proj_kernel(
    const float* __restrict__ pw, const float* __restrict__ pb, float* __restrict__ out)
{
    __shared__ float xs[16][W];
    size_t t0 = (size_t)blockIdx.x * 16;
    for (int i = threadIdx.x; i < 16 * W; i += 256)
        xs[i >> 8][i & 255] = g_x[t0 * W + i];
    __syncthreads();
    if (threadIdx.x < 64) {
        int t = threadIdx.x >> 2, o = threadIdx.x & 3;
        float acc = pb[o];
#pragma unroll 8
        for (int c = 0; c < W; c++) acc += xs[t][c] * pw[c * CIN + o];
        out[(t0 + t) * CIN + o] = acc;
    }
}

// ---------------- launch ----------------
extern "C" void kernel_launch(void* const* d_in, const int* in_sizes, int n_in,
                              void* d_out, int out_size)
{
    const float* feat = (const float*)d_in[0];
    const float* coords = (const float*)d_in[1];
    const float* tn   = (const float*)d_in[2];
    const float* ew   = (const float*)d_in[3];
    const float* eb   = (const float*)d_in[4];
    const float* ln1g = (const float*)d_in[5];
    const float* ln1b = (const float*)d_in[6];
    const float* sw   = (const float*)d_in[7];
    const float* sb   = (const float*)d_in[8];
    const float* qkvw = (const float*)d_in[9];
    const float* qkvb = (const float*)d_in[10];
    const float* outw = (const float*)d_in[11];
    const float* outb = (const float*)d_in[12];
    const float* ln2g = (const float*)d_in[13];
    const float* ln2b = (const float*)d_in[14];
    const float* f1w  = (const float*)d_in[15];
    const float* f1b  = (const float*)d_in[16];
    const float* f2w  = (const float*)d_in[17];
    const float* f2b  = (const float*)d_in[18];
    const float* pw   = (const float*)d_in[19];
    const float* pb   = (const float*)d_in[20];

    static int attr_set = 0;
    if (!attr_set) {
        cudaFuncSetAttribute(ffn_mma_kernel, cudaFuncAttributeMaxDynamicSharedMemorySize, SM_FFN_BYTES);
        cudaFuncSetAttribute(latent_kernel, cudaFuncAttributeMaxDynamicSharedMemorySize, LAT_SMEM);
        attr_set = 1;
    }

    embed_kernel<<<B * N / 16, 256>>>(feat, coords, tn, ew, eb);              // 1
    w1t_kernel<<<L * FF * W / 256, 256>>>(f1w);                                // 2
    w2t_zero_kernel<<<NB_W2T + NB_Z + 1, 256>>>(f2w);                          // 3

    for (int l = 0; l < L; l++) {
        slice_kernel<<<B * (N / TOK1), 256>>>(ln1g, ln1b, sw, sb, l);          // 4, 7, ...
        latent_kernel<<<B, 512, LAT_SMEM>>>(qkvw, qkvb, outw, outb, l);        // 5, 8, ...
        ffn_mma_kernel<<<B * (N / TOKF), 256, SM_FFN_BYTES>>>(ln2g, ln2b, f1b, f2b, l);  // 6 <- profiled
    }

    proj_kernel<<<(B * N) / 16, 256>>>(pw, pb, (float*)d_out);
}